// round 4
// baseline (speedup 1.0000x reference)
#include <cuda_runtime.h>
#include <cuda.h>
#include <cstdint>
#include <cstddef>

// ============================================================================
// Problem dims
// ============================================================================
#define TOKENS 8192
#define DIN    2048
#define DOUT   8192

// GEMM tiling — TF32 mma.sync + cp.async multistage
#define BM 128
#define BN 256
#define BK 32                    // 32 fp32 = 128B row = swizzle atom
#define NSTAGE 4
#define NK (DIN/BK)              // 64

#define NWARP_M 2
#define NWARP_N 4
#define WM (BM/NWARP_M)          // 64
#define WN (BN/NWARP_N)          // 64
#define NTHREADS 256             // 8 compute warps

#define A_STAGE_BYTES (BM*BK*4)              // 16384
#define B_STAGE_BYTES (BN*BK*4)              // 32768
#define STAGE_BYTES   (A_STAGE_BYTES + B_STAGE_BYTES)  // 49152
#define SMEM_TOTAL    (NSTAGE*STAGE_BYTES)   // 196608

#define NA_CHUNK 4               // 16B chunks per thread per stage (A)
#define NB_CHUNK 8               // (B)

// ============================================================================
// Scratch
// ============================================================================
__device__ float g_A[(size_t)TOKENS * DIN];   // 64 MiB, FWHT output (tf32-rounded)

// ============================================================================
// Helpers
// ============================================================================
__device__ __forceinline__ uint32_t smem_to_u32(const void* p) {
    uint32_t a;
    asm("{ .reg .u64 t; cvta.to.shared.u64 t, %1; cvt.u32.u64 %0, t; }" : "=r"(a) : "l"(p));
    return a;
}

__device__ __forceinline__ void cpasync16(uint32_t dst, const float* src) {
    asm volatile("cp.async.cg.shared.global [%0], [%1], 16;" :: "r"(dst), "l"(src));
}

__device__ __forceinline__ uint32_t lds32(uint32_t addr) {
    uint32_t v;
    asm volatile("ld.shared.b32 %0, [%1];" : "=r"(v) : "r"(addr));
    return v;
}

__device__ __forceinline__ void mma_tf32(float* c, const uint32_t* a, const uint32_t* b) {
    asm volatile(
        "mma.sync.aligned.m16n8k8.row.col.f32.tf32.tf32.f32 "
        "{%0,%1,%2,%3}, {%4,%5,%6,%7}, {%8,%9}, {%0,%1,%2,%3};"
        : "+f"(c[0]), "+f"(c[1]), "+f"(c[2]), "+f"(c[3])
        : "r"(a[0]), "r"(a[1]), "r"(a[2]), "r"(a[3]), "r"(b[0]), "r"(b[1]));
}

// ============================================================================
// Kernel 1: per-row FWHT (fp32 in smem) + round-to-tf32 -> g_A
// ============================================================================
__global__ void __launch_bounds__(256) fwht_kernel(const float* __restrict__ x,
                                                   float* __restrict__ A) {
    __shared__ float s[DIN];
    const int row = blockIdx.x;
    const float* xr = x + (size_t)row * DIN;
    for (int i = threadIdx.x; i < DIN; i += 256) s[i] = xr[i];
    __syncthreads();
    #pragma unroll
    for (int h = 1; h < DIN; h <<= 1) {
        for (int p = threadIdx.x; p < DIN / 2; p += 256) {
            int i = ((p & ~(h - 1)) << 1) | (p & (h - 1));
            int j = i + h;
            float a = s[i], b = s[j];
            s[i] = a + b;
            s[j] = a - b;
        }
        __syncthreads();
    }
    const float scale = 0.022097086912079608f;  // 1/sqrt(2048)
    float* Ar = A + (size_t)row * DIN;
    for (int i = threadIdx.x; i < DIN; i += 256) {
        float v = s[i] * scale;
        uint32_t u;
        asm("cvt.rna.tf32.f32 %0, %1;" : "=r"(u) : "f"(v));  // pre-round once
        Ar[i] = __uint_as_float(u);
    }
}

// ============================================================================
// Kernel 2: TF32 GEMM, cp.async 4-stage pipeline, 128B XOR swizzle
//   out[t][o] = sum_k A[t][k] * W[o][k] + bias[o]
//   Swizzle: physical_byte(row, colbyte) = row*128 + (colbyte ^ ((row&7)*16))
//   (XOR applied to the FULL in-row byte offset — this was the R2/R3 OOB bug)
// ============================================================================
__global__ void __launch_bounds__(NTHREADS, 1)
gemm_kernel(const float* __restrict__ Ag,
            const float* __restrict__ Wg,
            const float* __restrict__ bias,
            float* __restrict__ out) {
    extern __shared__ char smem[];
    const uint32_t sb = smem_to_u32(smem);
    const int tid = threadIdx.x, wid = tid >> 5, lane = tid & 31;
    const int lr = lane >> 2, lc = lane & 3;

    // group-swizzled tile mapping (GROUP_M=8 for L2 locality)
    const int num_n = DOUT / BN;     // 32
    const int GROUP_M = 8;
    int bid = blockIdx.x;
    int per_grp = GROUP_M * num_n;   // 256
    int g = bid / per_grp;
    int pid_m = g * GROUP_M + (bid % per_grp) % GROUP_M;
    int pid_n = (bid % per_grp) / GROUP_M;
    const int m0 = pid_m * BM;
    const int n0 = pid_n * BN;

    // -------- per-thread cp.async source/dest (16B chunks, swizzled) --------
    const float* srcA[NA_CHUNK]; uint32_t dstA[NA_CHUNK];
    #pragma unroll
    for (int j = 0; j < NA_CHUNK; j++) {
        int idx = tid + NTHREADS * j;        // 0..1023
        int r = idx >> 3, c16 = idx & 7;
        srcA[j] = Ag + (size_t)(m0 + r) * DIN + c16 * 4;
        dstA[j] = (uint32_t)(r * 128 + ((c16 * 16) ^ ((r & 7) * 16)));
    }
    const float* srcB[NB_CHUNK]; uint32_t dstB[NB_CHUNK];
    #pragma unroll
    for (int j = 0; j < NB_CHUNK; j++) {
        int idx = tid + NTHREADS * j;        // 0..2047
        int r = idx >> 3, c16 = idx & 7;
        srcB[j] = Wg + (size_t)(n0 + r) * DIN + c16 * 4;
        dstB[j] = (uint32_t)(A_STAGE_BYTES + r * 128 + ((c16 * 16) ^ ((r & 7) * 16)));
    }

    // -------- prologue: fill stages 0..NSTAGE-2 ------------------------------
    #pragma unroll
    for (int pre = 0; pre < NSTAGE - 1; pre++) {
        const uint32_t stg = sb + pre * STAGE_BYTES;
        const int koff = pre * BK;
        #pragma unroll
        for (int j = 0; j < NA_CHUNK; j++) cpasync16(stg + dstA[j], srcA[j] + koff);
        #pragma unroll
        for (int j = 0; j < NB_CHUNK; j++) cpasync16(stg + dstB[j], srcB[j] + koff);
        asm volatile("cp.async.commit_group;" ::: "memory");
    }

    // -------- compute warp coordinates --------------------------------------
    const int warp_m = wid & 1;
    const int warp_n = wid >> 1;
    const int wm0 = warp_m * WM;
    const int wn0 = warp_n * WN;
    const uint32_t maskR = (uint32_t)(lr * 16);      // swizzle mask (lr in 0..7)
    const uint32_t colA  = (uint32_t)(lc * 4);       // base in-row col byte
    const uint32_t arow0 = (uint32_t)((wm0 + lr) * 128);
    const uint32_t brow0 = (uint32_t)(A_STAGE_BYTES + (wn0 + lr) * 128);

    float acc[WM / 16][WN / 8][4];
    #pragma unroll
    for (int mt = 0; mt < WM / 16; mt++)
        #pragma unroll
        for (int nt = 0; nt < WN / 8; nt++)
            #pragma unroll
            for (int q = 0; q < 4; q++) acc[mt][nt][q] = 0.0f;

    // -------- main loop ------------------------------------------------------
    for (int ki = 0; ki < NK; ki++) {
        const int slot = ki & (NSTAGE - 1);
        asm volatile("cp.async.wait_group %0;" :: "n"(NSTAGE - 2) : "memory");
        __syncthreads();

        const uint32_t stg = sb + slot * STAGE_BYTES;
        const uint32_t arow = stg + arow0;
        const uint32_t brow = stg + brow0;
        #pragma unroll
        for (int kk = 0; kk < BK / 8; kk++) {
            // full column byte XOR'd with the row mask (c1: bit4 of pre-XOR is 0)
            const uint32_t c0 = ((uint32_t)(kk * 32) + colA) ^ maskR;
            const uint32_t c1 = c0 ^ 16;
            uint32_t afr[WM / 16][4];
            uint32_t bfr[WN / 8][2];
            #pragma unroll
            for (int mt = 0; mt < WM / 16; mt++) {
                const uint32_t a0 = arow + mt * 2048;   // +16 rows
                afr[mt][0] = lds32(a0 + c0);
                afr[mt][1] = lds32(a0 + 1024 + c0);     // +8 rows, same mask
                afr[mt][2] = lds32(a0 + c1);
                afr[mt][3] = lds32(a0 + 1024 + c1);
            }
            #pragma unroll
            for (int nt = 0; nt < WN / 8; nt++) {
                const uint32_t b0 = brow + nt * 1024;   // +8 rows
                bfr[nt][0] = lds32(b0 + c0);
                bfr[nt][1] = lds32(b0 + c1);
            }
            #pragma unroll
            for (int mt = 0; mt < WM / 16; mt++)
                #pragma unroll
                for (int nt = 0; nt < WN / 8; nt++)
                    mma_tf32(acc[mt][nt], afr[mt], bfr[nt]);
        }

        // issue loads for chunk ki+NSTAGE-1 into the slot freed last iteration
        const int nk2 = ki + NSTAGE - 1;
        if (nk2 < NK) {
            const uint32_t stg2 = sb + (nk2 & (NSTAGE - 1)) * STAGE_BYTES;
            const int koff = nk2 * BK;
            #pragma unroll
            for (int j = 0; j < NA_CHUNK; j++) cpasync16(stg2 + dstA[j], srcA[j] + koff);
            #pragma unroll
            for (int j = 0; j < NB_CHUNK; j++) cpasync16(stg2 + dstB[j], srcB[j] + koff);
        }
        asm volatile("cp.async.commit_group;" ::: "memory");
    }

    // -------- epilogue: bias + store ----------------------------------------
    #pragma unroll
    for (int mt = 0; mt < WM / 16; mt++) {
        const int row0 = m0 + wm0 + mt * 16 + lr;
        float* o0 = out + (size_t)row0 * DOUT;
        float* o1 = o0 + (size_t)8 * DOUT;
        #pragma unroll
        for (int nt = 0; nt < WN / 8; nt++) {
            const int col = n0 + wn0 + nt * 8 + 2 * lc;
            const float2 bv = *reinterpret_cast<const float2*>(&bias[col]);
            float2 v0, v1;
            v0.x = acc[mt][nt][0] + bv.x;  v0.y = acc[mt][nt][1] + bv.y;
            v1.x = acc[mt][nt][2] + bv.x;  v1.y = acc[mt][nt][3] + bv.y;
            *reinterpret_cast<float2*>(o0 + col) = v0;
            *reinterpret_cast<float2*>(o1 + col) = v1;
        }
    }
}

// ============================================================================
// Host launch
// ============================================================================
extern "C" void kernel_launch(void* const* d_in, const int* in_sizes, int n_in,
                              void* d_out, int out_size) {
    const float* x    = (const float*)d_in[0];
    const float* w    = (const float*)d_in[1];
    const float* bias = (const float*)d_in[2];
    float* out        = (float*)d_out;

    float* dA = nullptr;
    cudaGetSymbolAddress((void**)&dA, g_A);

    // 1) FWHT + tf32 pre-round
    fwht_kernel<<<TOKENS, 256>>>(x, dA);

    // 2) GEMM (W fp32 consumed directly — exact in tf32 since values are fp8)
    cudaFuncSetAttribute(gemm_kernel, cudaFuncAttributeMaxDynamicSharedMemorySize, SMEM_TOTAL);
    dim3 grid((TOKENS / BM) * (DOUT / BN));  // 2048 CTAs, group-swizzled 1D
    gemm_kernel<<<grid, NTHREADS, SMEM_TOTAL>>>(dA, w, bias, out);
}

// round 8
// speedup vs baseline: 1.7881x; 1.7881x over previous
#include <cuda_runtime.h>
#include <cuda.h>
#include <cuda_fp16.h>
#include <cstdint>
#include <cstddef>

// ============================================================================
// Problem dims
// ============================================================================
#define TOKENS 8192
#define DIN    2048
#define DOUT   8192

// GEMM tiling — FP16 mma.sync m16n8k16 + cp.async multistage
#define BM 128
#define BN 256
#define BK 64                    // 64 halves = 128B row = swizzle atom
#define NSTAGE 4
#define NK (DIN/BK)              // 32

#define NWARP_M 2
#define NWARP_N 4
#define WM (BM/NWARP_M)          // 64
#define WN (BN/NWARP_N)          // 64
#define NTHREADS 256             // 8 compute warps

#define A_STAGE_BYTES (BM*BK*2)              // 16384
#define B_STAGE_BYTES (BN*BK*2)              // 32768
#define STAGE_BYTES   (A_STAGE_BYTES + B_STAGE_BYTES)  // 49152
#define SMEM_TOTAL    (NSTAGE*STAGE_BYTES)   // 196608

#define NA_CHUNK 4               // 16B chunks per thread per stage (A)
#define NB_CHUNK 8               // (B)

// ============================================================================
// Scratch
// ============================================================================
__device__ __half g_A[(size_t)TOKENS * DIN];   // 32 MiB, FWHT output (fp16)
__device__ __half g_B[(size_t)DOUT   * DIN];   // 32 MiB, W in fp16 (exact)

// ============================================================================
// Helpers
// ============================================================================
__device__ __forceinline__ uint32_t smem_to_u32(const void* p) {
    uint32_t a;
    asm("{ .reg .u64 t; cvta.to.shared.u64 t, %1; cvt.u32.u64 %0, t; }" : "=r"(a) : "l"(p));
    return a;
}

__device__ __forceinline__ void cpasync16(uint32_t dst, const __half* src) {
    asm volatile("cp.async.cg.shared.global [%0], [%1], 16;" :: "r"(dst), "l"(src));
}

__device__ __forceinline__ uint32_t lds32(uint32_t addr) {
    uint32_t v;
    asm volatile("ld.shared.b32 %0, [%1];" : "=r"(v) : "r"(addr));
    return v;
}

__device__ __forceinline__ void mma_f16(float* c, const uint32_t* a, const uint32_t* b) {
    asm volatile(
        "mma.sync.aligned.m16n8k16.row.col.f32.f16.f16.f32 "
        "{%0,%1,%2,%3}, {%4,%5,%6,%7}, {%8,%9}, {%0,%1,%2,%3};"
        : "+f"(c[0]), "+f"(c[1]), "+f"(c[2]), "+f"(c[3])
        : "r"(a[0]), "r"(a[1]), "r"(a[2]), "r"(a[3]), "r"(b[0]), "r"(b[1]));
}

// ============================================================================
// Kernel 1: per-row FWHT (fp32 in smem) -> fp16 g_A
// ============================================================================
__global__ void __launch_bounds__(256) fwht_kernel(const float* __restrict__ x,
                                                   __half* __restrict__ A) {
    __shared__ float s[DIN];
    const int row = blockIdx.x;
    const float* xr = x + (size_t)row * DIN;
    for (int i = threadIdx.x; i < DIN; i += 256) s[i] = xr[i];
    __syncthreads();
    #pragma unroll
    for (int h = 1; h < DIN; h <<= 1) {
        for (int p = threadIdx.x; p < DIN / 2; p += 256) {
            int i = ((p & ~(h - 1)) << 1) | (p & (h - 1));
            int j = i + h;
            float a = s[i], b = s[j];
            s[i] = a + b;
            s[j] = a - b;
        }
        __syncthreads();
    }
    const float scale = 0.022097086912079608f;  // 1/sqrt(2048)
    __half* Ar = A + (size_t)row * DIN;
    for (int i = threadIdx.x; i < DIN; i += 256) {
        Ar[i] = __float2half(s[i] * scale);
    }
}

// ============================================================================
// Kernel 2: W fp32 -> fp16 (exact: values are fp8-e4m3 representable)
// ============================================================================
__global__ void __launch_bounds__(256) wconv_kernel(const float4* __restrict__ w4,
                                                    __half* __restrict__ B) {
    size_t n4 = (size_t)DOUT * DIN / 4;
    size_t i = (size_t)blockIdx.x * blockDim.x + threadIdx.x;
    if (i >= n4) return;
    float4 v = w4[i];
    __half2 p0 = __floats2half2_rn(v.x, v.y);
    __half2 p1 = __floats2half2_rn(v.z, v.w);
    __half2* dst = reinterpret_cast<__half2*>(B + i * 4);
    dst[0] = p0;
    dst[1] = p1;
}

// ============================================================================
// Kernel 3: FP16 GEMM, cp.async 4-stage pipeline, 128B XOR swizzle
//   out[t][o] = sum_k A[t][k] * W[o][k] + bias[o]
//   physical_byte(row, colbyte) = row*128 + (colbyte ^ ((row&7)*16))
// ============================================================================
__global__ void __launch_bounds__(NTHREADS, 1)
gemm_kernel(const __half* __restrict__ Ag,
            const __half* __restrict__ Wg,
            const float* __restrict__ bias,
            float* __restrict__ out) {
    extern __shared__ char smem[];
    const uint32_t sb = smem_to_u32(smem);
    const int tid = threadIdx.x, wid = tid >> 5, lane = tid & 31;
    const int lr = lane >> 2, lc = lane & 3;

    // group-swizzled tile mapping (GROUP_M=8 for L2 locality)
    const int num_n = DOUT / BN;     // 32
    const int GROUP_M = 8;
    int bid = blockIdx.x;
    int per_grp = GROUP_M * num_n;   // 256
    int g = bid / per_grp;
    int pid_m = g * GROUP_M + (bid % per_grp) % GROUP_M;
    int pid_n = (bid % per_grp) / GROUP_M;
    const int m0 = pid_m * BM;
    const int n0 = pid_n * BN;

    // -------- per-thread cp.async source/dest (16B chunks, swizzled) --------
    // tile row r holds 64 halves (128B); chunk c16 in [0,8)
    const __half* srcA[NA_CHUNK]; uint32_t dstA[NA_CHUNK];
    #pragma unroll
    for (int j = 0; j < NA_CHUNK; j++) {
        int idx = tid + NTHREADS * j;        // 0..1023
        int r = idx >> 3, c16 = idx & 7;
        srcA[j] = Ag + (size_t)(m0 + r) * DIN + c16 * 8;
        dstA[j] = (uint32_t)(r * 128 + ((c16 * 16) ^ ((r & 7) * 16)));
    }
    const __half* srcB[NB_CHUNK]; uint32_t dstB[NB_CHUNK];
    #pragma unroll
    for (int j = 0; j < NB_CHUNK; j++) {
        int idx = tid + NTHREADS * j;        // 0..2047
        int r = idx >> 3, c16 = idx & 7;
        srcB[j] = Wg + (size_t)(n0 + r) * DIN + c16 * 8;
        dstB[j] = (uint32_t)(A_STAGE_BYTES + r * 128 + ((c16 * 16) ^ ((r & 7) * 16)));
    }

    // -------- prologue: fill stages 0..NSTAGE-2 ------------------------------
    #pragma unroll
    for (int pre = 0; pre < NSTAGE - 1; pre++) {
        const uint32_t stg = sb + pre * STAGE_BYTES;
        const int koff = pre * BK;
        #pragma unroll
        for (int j = 0; j < NA_CHUNK; j++) cpasync16(stg + dstA[j], srcA[j] + koff);
        #pragma unroll
        for (int j = 0; j < NB_CHUNK; j++) cpasync16(stg + dstB[j], srcB[j] + koff);
        asm volatile("cp.async.commit_group;" ::: "memory");
    }

    // -------- compute warp coordinates --------------------------------------
    const int warp_m = wid & 1;
    const int warp_n = wid >> 1;
    const int wm0 = warp_m * WM;
    const int wn0 = warp_n * WN;
    const uint32_t maskR = (uint32_t)(lr * 16);      // swizzle mask (lr in 0..7)
    const uint32_t colA  = (uint32_t)(lc * 4);       // base in-row col byte
    const uint32_t arow0 = (uint32_t)((wm0 + lr) * 128);
    const uint32_t brow0 = (uint32_t)(A_STAGE_BYTES + (wn0 + lr) * 128);

    float acc[WM / 16][WN / 8][4];
    #pragma unroll
    for (int mt = 0; mt < WM / 16; mt++)
        #pragma unroll
        for (int nt = 0; nt < WN / 8; nt++)
            #pragma unroll
            for (int q = 0; q < 4; q++) acc[mt][nt][q] = 0.0f;

    // -------- main loop ------------------------------------------------------
    for (int ki = 0; ki < NK; ki++) {
        const int slot = ki & (NSTAGE - 1);
        asm volatile("cp.async.wait_group %0;" :: "n"(NSTAGE - 2) : "memory");
        __syncthreads();

        const uint32_t stg = sb + slot * STAGE_BYTES;
        const uint32_t arow = stg + arow0;
        const uint32_t brow = stg + brow0;
        #pragma unroll
        for (int kk = 0; kk < BK / 16; kk++) {       // 4 k-steps of 16 halves
            // m16n8k16 fp16 fragments:
            //   a0=(lr, k0..1) a1=(lr+8, k0..1) a2=(lr, k8..9) a3=(lr+8, k8..9)
            //   b0=(k0..1, n=lr) b1=(k8..9, n=lr)   (k pair = 2*lc halves = lc*4 bytes)
            const uint32_t c0 = ((uint32_t)(kk * 32) + colA) ^ maskR;
            const uint32_t c1 = c0 ^ 16;
            uint32_t afr[WM / 16][4];
            uint32_t bfr[WN / 8][2];
            #pragma unroll
            for (int mt = 0; mt < WM / 16; mt++) {
                const uint32_t a0 = arow + mt * 2048;   // +16 rows
                afr[mt][0] = lds32(a0 + c0);
                afr[mt][1] = lds32(a0 + 1024 + c0);     // +8 rows
                afr[mt][2] = lds32(a0 + c1);
                afr[mt][3] = lds32(a0 + 1024 + c1);
            }
            #pragma unroll
            for (int nt = 0; nt < WN / 8; nt++) {
                const uint32_t b0 = brow + nt * 1024;   // +8 rows
                bfr[nt][0] = lds32(b0 + c0);
                bfr[nt][1] = lds32(b0 + c1);
            }
            #pragma unroll
            for (int mt = 0; mt < WM / 16; mt++)
                #pragma unroll
                for (int nt = 0; nt < WN / 8; nt++)
                    mma_f16(acc[mt][nt], afr[mt], bfr[nt]);
        }

        // issue loads for chunk ki+NSTAGE-1 into the slot freed last iteration
        const int nk2 = ki + NSTAGE - 1;
        if (nk2 < NK) {
            const uint32_t stg2 = sb + (nk2 & (NSTAGE - 1)) * STAGE_BYTES;
            const int koff = nk2 * BK;
            #pragma unroll
            for (int j = 0; j < NA_CHUNK; j++) cpasync16(stg2 + dstA[j], srcA[j] + koff);
            #pragma unroll
            for (int j = 0; j < NB_CHUNK; j++) cpasync16(stg2 + dstB[j], srcB[j] + koff);
        }
        asm volatile("cp.async.commit_group;" ::: "memory");
    }

    // -------- epilogue: bias + store ----------------------------------------
    #pragma unroll
    for (int mt = 0; mt < WM / 16; mt++) {
        const int row0 = m0 + wm0 + mt * 16 + lr;
        float* o0 = out + (size_t)row0 * DOUT;
        float* o1 = o0 + (size_t)8 * DOUT;
        #pragma unroll
        for (int nt = 0; nt < WN / 8; nt++) {
            const int col = n0 + wn0 + nt * 8 + 2 * lc;
            const float2 bv = *reinterpret_cast<const float2*>(&bias[col]);
            float2 v0, v1;
            v0.x = acc[mt][nt][0] + bv.x;  v0.y = acc[mt][nt][1] + bv.y;
            v1.x = acc[mt][nt][2] + bv.x;  v1.y = acc[mt][nt][3] + bv.y;
            *reinterpret_cast<float2*>(o0 + col) = v0;
            *reinterpret_cast<float2*>(o1 + col) = v1;
        }
    }
}

// ============================================================================
// Host launch
// ============================================================================
extern "C" void kernel_launch(void* const* d_in, const int* in_sizes, int n_in,
                              void* d_out, int out_size) {
    const float* x    = (const float*)d_in[0];
    const float* w    = (const float*)d_in[1];
    const float* bias = (const float*)d_in[2];
    float* out        = (float*)d_out;

    __half *dA = nullptr, *dB = nullptr;
    cudaGetSymbolAddress((void**)&dA, g_A);
    cudaGetSymbolAddress((void**)&dB, g_B);

    // 1) FWHT -> fp16
    fwht_kernel<<<TOKENS, 256>>>(x, dA);

    // 2) W -> fp16 (exact for fp8-valued W)
    {
        size_t n4 = (size_t)DOUT * DIN / 4;
        wconv_kernel<<<(unsigned)((n4 + 255) / 256), 256>>>((const float4*)w, dB);
    }

    // 3) GEMM
    cudaFuncSetAttribute(gemm_kernel, cudaFuncAttributeMaxDynamicSharedMemorySize, SMEM_TOTAL);
    dim3 grid((TOKENS / BM) * (DOUT / BN));  // 2048 CTAs, group-swizzled 1D
    gemm_kernel<<<grid, NTHREADS, SMEM_TOTAL>>>(dA, dB, bias, out);
}

// round 9
// speedup vs baseline: 1.9241x; 1.0760x over previous
#include <cuda_runtime.h>
#include <cuda.h>
#include <cuda_fp16.h>
#include <cstdint>
#include <cstddef>

// ============================================================================
// Problem dims
// ============================================================================
#define TOKENS 8192
#define DIN    2048
#define DOUT   8192

// GEMM tiling — FP16 mma.sync m16n8k16 + cp.async, 2 CTAs/SM for occupancy
#define BM 128
#define BN 128
#define BK 64                    // 64 halves = 128B row = swizzle atom
#define NSTAGE 3
#define NK (DIN/BK)              // 32

#define NWARP_M 2
#define NWARP_N 4
#define WM (BM/NWARP_M)          // 64
#define WN (BN/NWARP_N)          // 32
#define NTHREADS 256             // 8 compute warps

#define A_STAGE_BYTES (BM*BK*2)              // 16384
#define B_STAGE_BYTES (BN*BK*2)              // 16384
#define STAGE_BYTES   (A_STAGE_BYTES + B_STAGE_BYTES)  // 32768
#define SMEM_TOTAL    (NSTAGE*STAGE_BYTES)   // 98304 (2 CTAs/SM: 192KB < 228KB)

#define NA_CHUNK 4               // 16B chunks per thread per stage (A)
#define NB_CHUNK 4               // (B)

// ============================================================================
// Scratch
// ============================================================================
__device__ __half g_A[(size_t)TOKENS * DIN];   // 32 MiB, FWHT output (fp16)
__device__ __half g_B[(size_t)DOUT   * DIN];   // 32 MiB, W in fp16 (exact)

// ============================================================================
// Helpers
// ============================================================================
__device__ __forceinline__ uint32_t smem_to_u32(const void* p) {
    uint32_t a;
    asm("{ .reg .u64 t; cvta.to.shared.u64 t, %1; cvt.u32.u64 %0, t; }" : "=r"(a) : "l"(p));
    return a;
}

__device__ __forceinline__ void cpasync16(uint32_t dst, const __half* src) {
    asm volatile("cp.async.cg.shared.global [%0], [%1], 16;" :: "r"(dst), "l"(src));
}

__device__ __forceinline__ uint32_t lds32(uint32_t addr) {
    uint32_t v;
    asm volatile("ld.shared.b32 %0, [%1];" : "=r"(v) : "r"(addr));
    return v;
}

__device__ __forceinline__ void mma_f16(float* c, const uint32_t* a, const uint32_t* b) {
    asm volatile(
        "mma.sync.aligned.m16n8k16.row.col.f32.f16.f16.f32 "
        "{%0,%1,%2,%3}, {%4,%5,%6,%7}, {%8,%9}, {%0,%1,%2,%3};"
        : "+f"(c[0]), "+f"(c[1]), "+f"(c[2]), "+f"(c[3])
        : "r"(a[0]), "r"(a[1]), "r"(a[2]), "r"(a[3]), "r"(b[0]), "r"(b[1]));
}

// ============================================================================
// Kernel 1: per-row FWHT, register+shuffle version -> fp16 g_A
//   8 elems/thread (idx = 8t+e): h=1,2,4 in-register; h=8..128 via shfl.bfly
//   (lane bits); h=256,512,1024 via 3 smem exchange rounds (warp bits).
//   Butterflies on distinct index bits commute, so order is free.
// ============================================================================
__global__ void __launch_bounds__(256) fwht_kernel(const float* __restrict__ x,
                                                   __half* __restrict__ A) {
    __shared__ float s[DIN];
    const int t = threadIdx.x;
    const int lane = t & 31, w = t >> 5;      // 8 warps
    const float* xr = x + (size_t)blockIdx.x * DIN;

    float v[8];
    {
        float4 f0 = *reinterpret_cast<const float4*>(xr + 8 * t);
        float4 f1 = *reinterpret_cast<const float4*>(xr + 8 * t + 4);
        v[0] = f0.x; v[1] = f0.y; v[2] = f0.z; v[3] = f0.w;
        v[4] = f1.x; v[5] = f1.y; v[6] = f1.z; v[7] = f1.w;
    }
    // ---- in-register: h = 1, 2, 4 (bits 0..2 of element index) ----
    #pragma unroll
    for (int hb = 1; hb <= 4; hb <<= 1) {
        #pragma unroll
        for (int e = 0; e < 8; e++) {
            if (!(e & hb)) {
                float a = v[e], b = v[e | hb];
                v[e] = a + b;
                v[e | hb] = a - b;
            }
        }
    }
    // ---- shuffle: h = 8,16,32,64,128 (lane bits 0..4) ----
    #pragma unroll
    for (int mask = 1; mask <= 16; mask <<= 1) {
        #pragma unroll
        for (int e = 0; e < 8; e++) {
            float o = __shfl_xor_sync(0xFFFFFFFFu, v[e], mask);
            v[e] = (lane & mask) ? (o - v[e]) : (v[e] + o);
        }
    }
    // ---- smem exchange: h = 256,512,1024 (warp bits 0..2) ----
    *reinterpret_cast<float4*>(&s[8 * t])     = make_float4(v[0], v[1], v[2], v[3]);
    *reinterpret_cast<float4*>(&s[8 * t + 4]) = make_float4(v[4], v[5], v[6], v[7]);
    __syncthreads();
    #pragma unroll
    for (int wb = 1; wb <= 4; wb <<= 1) {
        const int pt = (lane + 32 * (w ^ wb)) * 8;
        float4 o0 = *reinterpret_cast<const float4*>(&s[pt]);
        float4 o1 = *reinterpret_cast<const float4*>(&s[pt + 4]);
        float o[8] = {o0.x, o0.y, o0.z, o0.w, o1.x, o1.y, o1.z, o1.w};
        #pragma unroll
        for (int e = 0; e < 8; e++)
            v[e] = (w & wb) ? (o[e] - v[e]) : (v[e] + o[e]);
        if (wb < 4) {
            __syncthreads();   // all reads of the old state done
            *reinterpret_cast<float4*>(&s[8 * t])     = make_float4(v[0], v[1], v[2], v[3]);
            *reinterpret_cast<float4*>(&s[8 * t + 4]) = make_float4(v[4], v[5], v[6], v[7]);
            __syncthreads();
        }
    }
    // ---- scale + fp16 + coalesced 16B store ----
    const float scale = 0.022097086912079608f;  // 1/sqrt(2048)
    __half2 h[4];
    #pragma unroll
    for (int e = 0; e < 4; e++)
        h[e] = __floats2half2_rn(v[2 * e] * scale, v[2 * e + 1] * scale);
    *reinterpret_cast<uint4*>(A + (size_t)blockIdx.x * DIN + 8 * t) =
        *reinterpret_cast<uint4*>(h);
}

// ============================================================================
// Kernel 2: W fp32 -> fp16 (exact: values are fp8-e4m3 representable)
// ============================================================================
__global__ void __launch_bounds__(256) wconv_kernel(const float4* __restrict__ w4,
                                                    __half* __restrict__ B) {
    size_t n4 = (size_t)DOUT * DIN / 4;
    size_t i = (size_t)blockIdx.x * blockDim.x + threadIdx.x;
    if (i >= n4) return;
    float4 v = w4[i];
    __half2 p0 = __floats2half2_rn(v.x, v.y);
    __half2 p1 = __floats2half2_rn(v.z, v.w);
    __half2* dst = reinterpret_cast<__half2*>(B + i * 4);
    dst[0] = p0;
    dst[1] = p1;
}

// ============================================================================
// Kernel 3: FP16 GEMM, cp.async 3-stage pipeline, 128B XOR swizzle, 2 CTAs/SM
//   out[t][o] = sum_k A[t][k] * W[o][k] + bias[o]
//   physical_byte(row, colbyte) = row*128 + (colbyte ^ ((row&7)*16))
// ============================================================================
__global__ void __launch_bounds__(NTHREADS, 2)
gemm_kernel(const __half* __restrict__ Ag,
            const __half* __restrict__ Wg,
            const float* __restrict__ bias,
            float* __restrict__ out) {
    extern __shared__ char smem[];
    const uint32_t sb = smem_to_u32(smem);
    const int tid = threadIdx.x, wid = tid >> 5, lane = tid & 31;
    const int lr = lane >> 2, lc = lane & 3;

    // group-swizzled tile mapping (GROUP_M=8 for L2 locality)
    const int num_n = DOUT / BN;     // 64
    const int GROUP_M = 8;
    int bid = blockIdx.x;
    int per_grp = GROUP_M * num_n;   // 512
    int g = bid / per_grp;
    int pid_m = g * GROUP_M + (bid % per_grp) % GROUP_M;
    int pid_n = (bid % per_grp) / GROUP_M;
    const int m0 = pid_m * BM;
    const int n0 = pid_n * BN;

    // -------- per-thread cp.async source/dest (16B chunks, swizzled) --------
    const __half* srcA[NA_CHUNK]; uint32_t dstA[NA_CHUNK];
    #pragma unroll
    for (int j = 0; j < NA_CHUNK; j++) {
        int idx = tid + NTHREADS * j;        // 0..1023
        int r = idx >> 3, c16 = idx & 7;
        srcA[j] = Ag + (size_t)(m0 + r) * DIN + c16 * 8;
        dstA[j] = (uint32_t)(r * 128 + ((c16 * 16) ^ ((r & 7) * 16)));
    }
    const __half* srcB[NB_CHUNK]; uint32_t dstB[NB_CHUNK];
    #pragma unroll
    for (int j = 0; j < NB_CHUNK; j++) {
        int idx = tid + NTHREADS * j;        // 0..1023
        int r = idx >> 3, c16 = idx & 7;
        srcB[j] = Wg + (size_t)(n0 + r) * DIN + c16 * 8;
        dstB[j] = (uint32_t)(A_STAGE_BYTES + r * 128 + ((c16 * 16) ^ ((r & 7) * 16)));
    }

    // -------- prologue: fill stages 0..NSTAGE-2 ------------------------------
    #pragma unroll
    for (int pre = 0; pre < NSTAGE - 1; pre++) {
        const uint32_t stg = sb + pre * STAGE_BYTES;
        const int koff = pre * BK;
        #pragma unroll
        for (int j = 0; j < NA_CHUNK; j++) cpasync16(stg + dstA[j], srcA[j] + koff);
        #pragma unroll
        for (int j = 0; j < NB_CHUNK; j++) cpasync16(stg + dstB[j], srcB[j] + koff);
        asm volatile("cp.async.commit_group;" ::: "memory");
    }

    // -------- compute warp coordinates --------------------------------------
    const int warp_m = wid & 1;
    const int warp_n = wid >> 1;
    const int wm0 = warp_m * WM;     // 0/64
    const int wn0 = warp_n * WN;     // 0..96
    const uint32_t maskR = (uint32_t)(lr * 16);
    const uint32_t colA  = (uint32_t)(lc * 4);
    const uint32_t arow0 = (uint32_t)((wm0 + lr) * 128);
    const uint32_t brow0 = (uint32_t)(A_STAGE_BYTES + (wn0 + lr) * 128);

    float acc[WM / 16][WN / 8][4];   // [4][4][4] = 64 regs
    #pragma unroll
    for (int mt = 0; mt < WM / 16; mt++)
        #pragma unroll
        for (int nt = 0; nt < WN / 8; nt++)
            #pragma unroll
            for (int q = 0; q < 4; q++) acc[mt][nt][q] = 0.0f;

    // -------- main loop (NSTAGE=3: explicit rotating slots) ------------------
    int slot = 0;                    // consumer slot
    int slot2 = NSTAGE - 1;          // producer slot (ki + NSTAGE-1)
    for (int ki = 0; ki < NK; ki++) {
        asm volatile("cp.async.wait_group %0;" :: "n"(NSTAGE - 2) : "memory");
        __syncthreads();

        const uint32_t stg = sb + slot * STAGE_BYTES;
        const uint32_t arow = stg + arow0;
        const uint32_t brow = stg + brow0;
        #pragma unroll
        for (int kk = 0; kk < BK / 16; kk++) {
            const uint32_t c0 = ((uint32_t)(kk * 32) + colA) ^ maskR;
            const uint32_t c1 = c0 ^ 16;
            uint32_t afr[WM / 16][4];
            uint32_t bfr[WN / 8][2];
            #pragma unroll
            for (int mt = 0; mt < WM / 16; mt++) {
                const uint32_t a0 = arow + mt * 2048;
                afr[mt][0] = lds32(a0 + c0);
                afr[mt][1] = lds32(a0 + 1024 + c0);
                afr[mt][2] = lds32(a0 + c1);
                afr[mt][3] = lds32(a0 + 1024 + c1);
            }
            #pragma unroll
            for (int nt = 0; nt < WN / 8; nt++) {
                const uint32_t b0 = brow + nt * 1024;
                bfr[nt][0] = lds32(b0 + c0);
                bfr[nt][1] = lds32(b0 + c1);
            }
            #pragma unroll
            for (int mt = 0; mt < WM / 16; mt++)
                #pragma unroll
                for (int nt = 0; nt < WN / 8; nt++)
                    mma_f16(acc[mt][nt], afr[mt], bfr[nt]);
        }

        // issue loads for chunk ki+NSTAGE-1 into the slot freed last iteration
        const int nk2 = ki + NSTAGE - 1;
        if (nk2 < NK) {
            const uint32_t stg2 = sb + slot2 * STAGE_BYTES;
            const int koff = nk2 * BK;
            #pragma unroll
            for (int j = 0; j < NA_CHUNK; j++) cpasync16(stg2 + dstA[j], srcA[j] + koff);
            #pragma unroll
            for (int j = 0; j < NB_CHUNK; j++) cpasync16(stg2 + dstB[j], srcB[j] + koff);
        }
        asm volatile("cp.async.commit_group;" ::: "memory");

        if (++slot == NSTAGE) slot = 0;
        if (++slot2 == NSTAGE) slot2 = 0;
    }

    // -------- epilogue: bias + store ----------------------------------------
    #pragma unroll
    for (int mt = 0; mt < WM / 16; mt++) {
        const int row0 = m0 + wm0 + mt * 16 + lr;
        float* o0 = out + (size_t)row0 * DOUT;
        float* o1 = o0 + (size_t)8 * DOUT;
        #pragma unroll
        for (int nt = 0; nt < WN / 8; nt++) {
            const int col = n0 + wn0 + nt * 8 + 2 * lc;
            const float2 bv = *reinterpret_cast<const float2*>(&bias[col]);
            float2 v0, v1;
            v0.x = acc[mt][nt][0] + bv.x;  v0.y = acc[mt][nt][1] + bv.y;
            v1.x = acc[mt][nt][2] + bv.x;  v1.y = acc[mt][nt][3] + bv.y;
            *reinterpret_cast<float2*>(o0 + col) = v0;
            *reinterpret_cast<float2*>(o1 + col) = v1;
        }
    }
}

// ============================================================================
// Host launch
// ============================================================================
extern "C" void kernel_launch(void* const* d_in, const int* in_sizes, int n_in,
                              void* d_out, int out_size) {
    const float* x    = (const float*)d_in[0];
    const float* w    = (const float*)d_in[1];
    const float* bias = (const float*)d_in[2];
    float* out        = (float*)d_out;

    __half *dA = nullptr, *dB = nullptr;
    cudaGetSymbolAddress((void**)&dA, g_A);
    cudaGetSymbolAddress((void**)&dB, g_B);

    // 1) FWHT -> fp16 (register + shuffle version)
    fwht_kernel<<<TOKENS, 256>>>(x, dA);

    // 2) W -> fp16 (exact for fp8-valued W)
    {
        size_t n4 = (size_t)DOUT * DIN / 4;
        wconv_kernel<<<(unsigned)((n4 + 255) / 256), 256>>>((const float4*)w, dB);
    }

    // 3) GEMM (2 CTAs/SM)
    cudaFuncSetAttribute(gemm_kernel, cudaFuncAttributeMaxDynamicSharedMemorySize, SMEM_TOTAL);
    dim3 grid((TOKENS / BM) * (DOUT / BN));  // 4096 CTAs, group-swizzled 1D
    gemm_kernel<<<grid, NTHREADS, SMEM_TOTAL>>>(dA, dB, bias, out);
}

// round 10
// speedup vs baseline: 2.1872x; 1.1367x over previous
#include <cuda_runtime.h>
#include <cuda.h>
#include <cuda_fp16.h>
#include <cstdint>
#include <cstddef>

// ============================================================================
// Problem dims
// ============================================================================
#define TOKENS 8192
#define DIN    2048
#define DOUT   8192

// GEMM tiling — FP16 mma.sync m16n8k16 + cp.async + ldmatrix, 2 CTAs/SM
#define BM 128
#define BN 128
#define BK 64                    // 64 halves = 128B row = swizzle atom
#define NSTAGE 3
#define NK (DIN/BK)              // 32

#define NWARP_M 2
#define NWARP_N 4
#define WM (BM/NWARP_M)          // 64
#define WN (BN/NWARP_N)          // 32
#define NTHREADS 256             // 8 compute warps

#define A_STAGE_BYTES (BM*BK*2)              // 16384
#define B_STAGE_BYTES (BN*BK*2)              // 16384
#define STAGE_BYTES   (A_STAGE_BYTES + B_STAGE_BYTES)  // 32768
#define SMEM_TOTAL    (NSTAGE*STAGE_BYTES)   // 98304 -> 2 CTAs/SM

#define NA_CHUNK 4               // 16B chunks per thread per stage (A)
#define NB_CHUNK 4               // (B)

// ============================================================================
// Scratch
// ============================================================================
__device__ __half g_A[(size_t)TOKENS * DIN];   // 32 MiB, FWHT output (fp16)
__device__ __half g_B[(size_t)DOUT   * DIN];   // 32 MiB, W in fp16 (exact)

// ============================================================================
// Helpers
// ============================================================================
__device__ __forceinline__ uint32_t smem_to_u32(const void* p) {
    uint32_t a;
    asm("{ .reg .u64 t; cvta.to.shared.u64 t, %1; cvt.u32.u64 %0, t; }" : "=r"(a) : "l"(p));
    return a;
}

__device__ __forceinline__ void cpasync16(uint32_t dst, const __half* src) {
    asm volatile("cp.async.cg.shared.global [%0], [%1], 16;" :: "r"(dst), "l"(src));
}

__device__ __forceinline__ void ldsm_x4(uint32_t* r, uint32_t addr) {
    asm volatile("ldmatrix.sync.aligned.m8n8.x4.shared.b16 {%0,%1,%2,%3}, [%4];"
        : "=r"(r[0]), "=r"(r[1]), "=r"(r[2]), "=r"(r[3]) : "r"(addr));
}

__device__ __forceinline__ void mma_f16(float* c, const uint32_t* a, const uint32_t* b) {
    asm volatile(
        "mma.sync.aligned.m16n8k16.row.col.f32.f16.f16.f32 "
        "{%0,%1,%2,%3}, {%4,%5,%6,%7}, {%8,%9}, {%0,%1,%2,%3};"
        : "+f"(c[0]), "+f"(c[1]), "+f"(c[2]), "+f"(c[3])
        : "r"(a[0]), "r"(a[1]), "r"(a[2]), "r"(a[3]), "r"(b[0]), "r"(b[1]));
}

// ============================================================================
// Kernel 1: per-row FWHT, 1 smem round-trip -> fp16 g_A
//   Phase 1: load idx = t + 256e (strided) -> reg butterflies on idx bits 8-10
//            (h = 256, 512, 1024)
//   transpose through smem (single __syncthreads)
//   Phase 2: load idx = 8t + e -> reg butterflies bits 0-2 (h = 1,2,4),
//            shfl.bfly bits 3-7 (h = 8..128). All levels commute (disjoint bits).
// ============================================================================
__global__ void __launch_bounds__(256) fwht_kernel(const float* __restrict__ x,
                                                   __half* __restrict__ A) {
    __shared__ float s[DIN];
    const int t = threadIdx.x;
    const int lane = t & 31;
    const float* xr = x + (size_t)blockIdx.x * DIN;

    float v[8];
    // ---- phase 1: strided load, butterflies on bits 8-10 (= e bits) ----
    #pragma unroll
    for (int e = 0; e < 8; e++) v[e] = xr[t + 256 * e];
    #pragma unroll
    for (int hb = 1; hb <= 4; hb <<= 1) {
        #pragma unroll
        for (int e = 0; e < 8; e++) {
            if (!(e & hb)) {
                float a = v[e], b = v[e | hb];
                v[e] = a + b;
                v[e | hb] = a - b;
            }
        }
    }
    // ---- transpose via smem (one round trip) ----
    #pragma unroll
    for (int e = 0; e < 8; e++) s[t + 256 * e] = v[e];
    __syncthreads();
    {
        float4 f0 = *reinterpret_cast<const float4*>(&s[8 * t]);
        float4 f1 = *reinterpret_cast<const float4*>(&s[8 * t + 4]);
        v[0] = f0.x; v[1] = f0.y; v[2] = f0.z; v[3] = f0.w;
        v[4] = f1.x; v[5] = f1.y; v[6] = f1.z; v[7] = f1.w;
    }
    // ---- phase 2a: bits 0-2 in-register (h = 1,2,4) ----
    #pragma unroll
    for (int hb = 1; hb <= 4; hb <<= 1) {
        #pragma unroll
        for (int e = 0; e < 8; e++) {
            if (!(e & hb)) {
                float a = v[e], b = v[e | hb];
                v[e] = a + b;
                v[e | hb] = a - b;
            }
        }
    }
    // ---- phase 2b: bits 3-7 via shuffles (h = 8..128) ----
    #pragma unroll
    for (int mask = 1; mask <= 16; mask <<= 1) {
        #pragma unroll
        for (int e = 0; e < 8; e++) {
            float o = __shfl_xor_sync(0xFFFFFFFFu, v[e], mask);
            v[e] = (lane & mask) ? (o - v[e]) : (v[e] + o);
        }
    }
    // ---- scale + fp16 + coalesced 16B store ----
    const float scale = 0.022097086912079608f;  // 1/sqrt(2048)
    __half2 h[4];
    #pragma unroll
    for (int e = 0; e < 4; e++)
        h[e] = __floats2half2_rn(v[2 * e] * scale, v[2 * e + 1] * scale);
    *reinterpret_cast<uint4*>(A + (size_t)blockIdx.x * DIN + 8 * t) =
        *reinterpret_cast<uint4*>(h);
}

// ============================================================================
// Kernel 2: W fp32 -> fp16 (exact: values are fp8-e4m3 representable)
// ============================================================================
__global__ void __launch_bounds__(256) wconv_kernel(const float4* __restrict__ w4,
                                                    __half* __restrict__ B) {
    size_t n4 = (size_t)DOUT * DIN / 4;
    size_t i = (size_t)blockIdx.x * blockDim.x + threadIdx.x;
    if (i >= n4) return;
    float4 v = w4[i];
    __half2 p0 = __floats2half2_rn(v.x, v.y);
    __half2 p1 = __floats2half2_rn(v.z, v.w);
    __half2* dst = reinterpret_cast<__half2*>(B + i * 4);
    dst[0] = p0;
    dst[1] = p1;
}

// ============================================================================
// Kernel 3: FP16 GEMM, cp.async 3-stage + ldmatrix fragments, 2 CTAs/SM
//   out[t][o] = sum_k A[t][k] * W[o][k] + bias[o]
//   smem: physical_byte(row, colbyte) = row*128 + (colbyte ^ ((row&7)*16))
// ============================================================================
__global__ void __launch_bounds__(NTHREADS, 2)
gemm_kernel(const __half* __restrict__ Ag,
            const __half* __restrict__ Wg,
            const float* __restrict__ bias,
            float* __restrict__ out) {
    extern __shared__ char smem[];
    const uint32_t sb = smem_to_u32(smem);
    const int tid = threadIdx.x, wid = tid >> 5, lane = tid & 31;
    const int lr = lane >> 2, lc = lane & 3;

    // group-swizzled tile mapping (GROUP_M=8 for L2 locality)
    const int num_n = DOUT / BN;     // 64
    const int GROUP_M = 8;
    int bid = blockIdx.x;
    int per_grp = GROUP_M * num_n;   // 512
    int g = bid / per_grp;
    int pid_m = g * GROUP_M + (bid % per_grp) % GROUP_M;
    int pid_n = (bid % per_grp) / GROUP_M;
    const int m0 = pid_m * BM;
    const int n0 = pid_n * BN;

    // -------- per-thread cp.async source/dest (16B chunks, swizzled) --------
    const __half* srcA[NA_CHUNK]; uint32_t dstA[NA_CHUNK];
    #pragma unroll
    for (int j = 0; j < NA_CHUNK; j++) {
        int idx = tid + NTHREADS * j;        // 0..1023
        int r = idx >> 3, c16 = idx & 7;
        srcA[j] = Ag + (size_t)(m0 + r) * DIN + c16 * 8;
        dstA[j] = (uint32_t)(r * 128 + ((c16 * 16) ^ ((r & 7) * 16)));
    }
    const __half* srcB[NB_CHUNK]; uint32_t dstB[NB_CHUNK];
    #pragma unroll
    for (int j = 0; j < NB_CHUNK; j++) {
        int idx = tid + NTHREADS * j;        // 0..1023
        int r = idx >> 3, c16 = idx & 7;
        srcB[j] = Wg + (size_t)(n0 + r) * DIN + c16 * 8;
        dstB[j] = (uint32_t)(A_STAGE_BYTES + r * 128 + ((c16 * 16) ^ ((r & 7) * 16)));
    }

    // -------- prologue: fill stages 0..NSTAGE-2 ------------------------------
    #pragma unroll
    for (int pre = 0; pre < NSTAGE - 1; pre++) {
        const uint32_t stg = sb + pre * STAGE_BYTES;
        const int koff = pre * BK;
        #pragma unroll
        for (int j = 0; j < NA_CHUNK; j++) cpasync16(stg + dstA[j], srcA[j] + koff);
        #pragma unroll
        for (int j = 0; j < NB_CHUNK; j++) cpasync16(stg + dstB[j], srcB[j] + koff);
        asm volatile("cp.async.commit_group;" ::: "memory");
    }

    // -------- compute warp coordinates + ldmatrix lane addressing -----------
    const int warp_m = wid & 1;
    const int warp_n = wid >> 1;
    const int wm0 = warp_m * WM;     // 0/64
    const int wn0 = warp_n * WN;     // 0..96

    // A x4: matrices j = lane>>3: j0 = (m..m+7, k0-7), j1 = (m+8.., k0-7),
    //       j2 = (m.., k8-15), j3 = (m+8.., k8-15); lane row r8 = lane&7
    const int r8 = lane & 7;
    const uint32_t maskL   = (uint32_t)(r8 * 16);            // swizzle mask
    const int aRow  = wm0 + ((lane >> 3) & 1) * 8 + r8;      // + mt*16
    const uint32_t aHi16 = (uint32_t)(((lane >> 4) & 1) * 16);
    const uint32_t aRowByte = (uint32_t)(aRow * 128);
    // B x4 (pair p covers nt=2p,2p+1): j0 = (n-rows nt0, k0-7), j1 = (nt0, k8-15),
    //       j2 = (nt1, k0-7), j3 = (nt1, k8-15)
    const int bRow  = wn0 + ((lane >> 4) & 1) * 8 + r8;      // + p*16
    const uint32_t bHi16 = (uint32_t)(((lane >> 3) & 1) * 16);
    const uint32_t bRowByte = (uint32_t)(A_STAGE_BYTES + bRow * 128);

    float acc[WM / 16][WN / 8][4];   // [4][4][4] = 64 regs
    #pragma unroll
    for (int mt = 0; mt < WM / 16; mt++)
        #pragma unroll
        for (int nt = 0; nt < WN / 8; nt++)
            #pragma unroll
            for (int q = 0; q < 4; q++) acc[mt][nt][q] = 0.0f;

    // -------- main loop ------------------------------------------------------
    int slot = 0;
    int slot2 = NSTAGE - 1;
    for (int ki = 0; ki < NK; ki++) {
        asm volatile("cp.async.wait_group %0;" :: "n"(NSTAGE - 2) : "memory");
        __syncthreads();

        const uint32_t stg = sb + slot * STAGE_BYTES;
        #pragma unroll
        for (int kk = 0; kk < BK / 16; kk++) {
            const uint32_t aCol = ((uint32_t)(kk * 32) + aHi16) ^ maskL;
            const uint32_t bCol = ((uint32_t)(kk * 32) + bHi16) ^ maskL;
            uint32_t afr[WM / 16][4];
            uint32_t bfr[WN / 8][2];
            #pragma unroll
            for (int mt = 0; mt < WM / 16; mt++)
                ldsm_x4(afr[mt], stg + aRowByte + mt * 2048 + aCol);
            #pragma unroll
            for (int p = 0; p < WN / 16; p++)
                ldsm_x4(&bfr[2 * p][0], stg + bRowByte + p * 2048 + bCol);
            #pragma unroll
            for (int mt = 0; mt < WM / 16; mt++)
                #pragma unroll
                for (int nt = 0; nt < WN / 8; nt++)
                    mma_f16(acc[mt][nt], afr[mt], bfr[nt]);
        }

        // issue loads for chunk ki+NSTAGE-1 into the slot freed last iteration
        const int nk2 = ki + NSTAGE - 1;
        if (nk2 < NK) {
            const uint32_t stg2 = sb + slot2 * STAGE_BYTES;
            const int koff = nk2 * BK;
            #pragma unroll
            for (int j = 0; j < NA_CHUNK; j++) cpasync16(stg2 + dstA[j], srcA[j] + koff);
            #pragma unroll
            for (int j = 0; j < NB_CHUNK; j++) cpasync16(stg2 + dstB[j], srcB[j] + koff);
        }
        asm volatile("cp.async.commit_group;" ::: "memory");

        if (++slot == NSTAGE) slot = 0;
        if (++slot2 == NSTAGE) slot2 = 0;
    }

    // -------- epilogue: bias + store ----------------------------------------
    #pragma unroll
    for (int mt = 0; mt < WM / 16; mt++) {
        const int row0 = m0 + wm0 + mt * 16 + lr;
        float* o0 = out + (size_t)row0 * DOUT;
        float* o1 = o0 + (size_t)8 * DOUT;
        #pragma unroll
        for (int nt = 0; nt < WN / 8; nt++) {
            const int col = n0 + wn0 + nt * 8 + 2 * lc;
            const float2 bv = *reinterpret_cast<const float2*>(&bias[col]);
            float2 v0, v1;
            v0.x = acc[mt][nt][0] + bv.x;  v0.y = acc[mt][nt][1] + bv.y;
            v1.x = acc[mt][nt][2] + bv.x;  v1.y = acc[mt][nt][3] + bv.y;
            *reinterpret_cast<float2*>(o0 + col) = v0;
            *reinterpret_cast<float2*>(o1 + col) = v1;
        }
    }
}

// ============================================================================
// Host launch
// ============================================================================
extern "C" void kernel_launch(void* const* d_in, const int* in_sizes, int n_in,
                              void* d_out, int out_size) {
    const float* x    = (const float*)d_in[0];
    const float* w    = (const float*)d_in[1];
    const float* bias = (const float*)d_in[2];
    float* out        = (float*)d_out;

    __half *dA = nullptr, *dB = nullptr;
    cudaGetSymbolAddress((void**)&dA, g_A);
    cudaGetSymbolAddress((void**)&dB, g_B);

    // 1) FWHT -> fp16 (single smem round-trip)
    fwht_kernel<<<TOKENS, 256>>>(x, dA);

    // 2) W -> fp16 (exact for fp8-valued W)
    {
        size_t n4 = (size_t)DOUT * DIN / 4;
        wconv_kernel<<<(unsigned)((n4 + 255) / 256), 256>>>((const float4*)w, dB);
    }

    // 3) GEMM (2 CTAs/SM, ldmatrix fragments)
    cudaFuncSetAttribute(gemm_kernel, cudaFuncAttributeMaxDynamicSharedMemorySize, SMEM_TOTAL);
    dim3 grid((TOKENS / BM) * (DOUT / BN));  // 4096 CTAs, group-swizzled 1D
    gemm_kernel<<<grid, NTHREADS, SMEM_TOTAL>>>(dA, dB, bias, out);
}

// round 11
// speedup vs baseline: 2.2019x; 1.0067x over previous
#include <cuda_runtime.h>
#include <cuda.h>
#include <cuda_fp16.h>
#include <cstdint>
#include <cstddef>

// ============================================================================
// Problem dims
// ============================================================================
#define TOKENS 8192
#define DIN    2048
#define DOUT   8192

// GEMM tiling — FP16 mma.sync m16n8k16, 4 warps x (64x64), 2 CTAs/SM
#define BM 128
#define BN 128
#define BK 64                    // 64 halves = 128B row = swizzle atom
#define NSTAGE 3
#define NK (DIN/BK)              // 32

#define NWARP_M 2
#define NWARP_N 2
#define WM (BM/NWARP_M)          // 64
#define WN (BN/NWARP_N)          // 64
#define NTHREADS 128             // 4 compute warps

#define A_STAGE_BYTES (BM*BK*2)              // 16384
#define B_STAGE_BYTES (BN*BK*2)              // 16384
#define STAGE_BYTES   (A_STAGE_BYTES + B_STAGE_BYTES)  // 32768
#define SMEM_TOTAL    (NSTAGE*STAGE_BYTES)   // 98304 -> 2 CTAs/SM

#define NCHUNK 8                 // 16B chunks per thread per stage (A and B each)

// ============================================================================
// Scratch
// ============================================================================
__device__ __half g_A[(size_t)TOKENS * DIN];   // 32 MiB, FWHT output (fp16)
__device__ __half g_B[(size_t)DOUT   * DIN];   // 32 MiB, W in fp16 (exact)

// ============================================================================
// Helpers
// ============================================================================
__device__ __forceinline__ uint32_t smem_to_u32(const void* p) {
    uint32_t a;
    asm("{ .reg .u64 t; cvta.to.shared.u64 t, %1; cvt.u32.u64 %0, t; }" : "=r"(a) : "l"(p));
    return a;
}

__device__ __forceinline__ void cpasync16(uint32_t dst, const __half* src) {
    asm volatile("cp.async.cg.shared.global [%0], [%1], 16;" :: "r"(dst), "l"(src));
}

__device__ __forceinline__ void ldsm_x4(uint32_t* r, uint32_t addr) {
    asm volatile("ldmatrix.sync.aligned.m8n8.x4.shared.b16 {%0,%1,%2,%3}, [%4];"
        : "=r"(r[0]), "=r"(r[1]), "=r"(r[2]), "=r"(r[3]) : "r"(addr));
}

__device__ __forceinline__ void mma_f16(float* c, const uint32_t* a, const uint32_t* b) {
    asm volatile(
        "mma.sync.aligned.m16n8k16.row.col.f32.f16.f16.f32 "
        "{%0,%1,%2,%3}, {%4,%5,%6,%7}, {%8,%9}, {%0,%1,%2,%3};"
        : "+f"(c[0]), "+f"(c[1]), "+f"(c[2]), "+f"(c[3])
        : "r"(a[0]), "r"(a[1]), "r"(a[2]), "r"(a[3]), "r"(b[0]), "r"(b[1]));
}

// ============================================================================
// Kernel 1 (fused prep): blocks [0, TOKENS) do per-row FWHT -> fp16 g_A;
// blocks [TOKENS, TOKENS+WCONV_BLOCKS) convert W fp32 -> fp16 g_B.
// Both phases are DRAM-bound and independent -> overlap in one launch.
// ============================================================================
#define WCONV_BLOCKS ((DOUT*DIN/4)/256)   // 16384 blocks, 1 float4 per thread

__global__ void __launch_bounds__(256) prep_kernel(const float* __restrict__ x,
                                                   const float4* __restrict__ w4,
                                                   __half* __restrict__ A,
                                                   __half* __restrict__ B) {
    if (blockIdx.x >= TOKENS) {
        // ---- wconv: exact fp32 -> fp16 (values are fp8-e4m3 representable) ----
        size_t i = (size_t)(blockIdx.x - TOKENS) * 256 + threadIdx.x;
        float4 v = w4[i];
        __half2 p0 = __floats2half2_rn(v.x, v.y);
        __half2 p1 = __floats2half2_rn(v.z, v.w);
        __half2* dst = reinterpret_cast<__half2*>(B + i * 4);
        dst[0] = p0;
        dst[1] = p1;
        return;
    }
    // ---- FWHT: 1 smem round-trip, reg + shuffle butterflies ----
    __shared__ float s[DIN];
    const int t = threadIdx.x;
    const int lane = t & 31;
    const float* xr = x + (size_t)blockIdx.x * DIN;

    float v[8];
    #pragma unroll
    for (int e = 0; e < 8; e++) v[e] = xr[t + 256 * e];
    #pragma unroll
    for (int hb = 1; hb <= 4; hb <<= 1) {       // h = 256,512,1024 (bits 8-10)
        #pragma unroll
        for (int e = 0; e < 8; e++) {
            if (!(e & hb)) {
                float a = v[e], b = v[e | hb];
                v[e] = a + b;
                v[e | hb] = a - b;
            }
        }
    }
    #pragma unroll
    for (int e = 0; e < 8; e++) s[t + 256 * e] = v[e];
    __syncthreads();
    {
        float4 f0 = *reinterpret_cast<const float4*>(&s[8 * t]);
        float4 f1 = *reinterpret_cast<const float4*>(&s[8 * t + 4]);
        v[0] = f0.x; v[1] = f0.y; v[2] = f0.z; v[3] = f0.w;
        v[4] = f1.x; v[5] = f1.y; v[6] = f1.z; v[7] = f1.w;
    }
    #pragma unroll
    for (int hb = 1; hb <= 4; hb <<= 1) {       // h = 1,2,4 (bits 0-2)
        #pragma unroll
        for (int e = 0; e < 8; e++) {
            if (!(e & hb)) {
                float a = v[e], b = v[e | hb];
                v[e] = a + b;
                v[e | hb] = a - b;
            }
        }
    }
    #pragma unroll
    for (int mask = 1; mask <= 16; mask <<= 1) { // h = 8..128 (bits 3-7)
        #pragma unroll
        for (int e = 0; e < 8; e++) {
            float o = __shfl_xor_sync(0xFFFFFFFFu, v[e], mask);
            v[e] = (lane & mask) ? (o - v[e]) : (v[e] + o);
        }
    }
    const float scale = 0.022097086912079608f;  // 1/sqrt(2048)
    __half2 h[4];
    #pragma unroll
    for (int e = 0; e < 4; e++)
        h[e] = __floats2half2_rn(v[2 * e] * scale, v[2 * e + 1] * scale);
    *reinterpret_cast<uint4*>(A + (size_t)blockIdx.x * DIN + 8 * t) =
        *reinterpret_cast<uint4*>(h);
}

// ============================================================================
// Kernel 2: FP16 GEMM, cp.async 3-stage + ldmatrix, 4 warps x (64x64)
//   out[t][o] = sum_k A[t][k] * W[o][k] + bias[o]
//   smem: physical_byte(row, colbyte) = row*128 + (colbyte ^ ((row&7)*16))
//   Chunk identity: chunk j = chunk0 + 16j rows -> src += 16j*DIN,
//   dst += 2048j (swizzle mask invariant under +16 rows).
// ============================================================================
__global__ void __launch_bounds__(NTHREADS, 2)
gemm_kernel(const __half* __restrict__ Ag,
            const __half* __restrict__ Wg,
            const float* __restrict__ bias,
            float* __restrict__ out) {
    extern __shared__ char smem[];
    const uint32_t sb = smem_to_u32(smem);
    const int tid = threadIdx.x, wid = tid >> 5, lane = tid & 31;
    const int lr = lane >> 2, lc = lane & 3;

    // group-swizzled tile mapping (GROUP_M=8 for L2 locality)
    const int num_n = DOUT / BN;     // 64
    const int GROUP_M = 8;
    int bid = blockIdx.x;
    int per_grp = GROUP_M * num_n;   // 512
    int g = bid / per_grp;
    int pid_m = g * GROUP_M + (bid % per_grp) % GROUP_M;
    int pid_n = (bid % per_grp) / GROUP_M;
    const int m0 = pid_m * BM;
    const int n0 = pid_n * BN;

    // -------- cp.async base addresses (chunk 0); j -> +16j*DIN / +2048j -----
    const int r0 = tid >> 3, c16 = tid & 7;
    const __half* srcA0 = Ag + (size_t)(m0 + r0) * DIN + c16 * 8;
    const __half* srcB0 = Wg + (size_t)(n0 + r0) * DIN + c16 * 8;
    const uint32_t dst0 = (uint32_t)(r0 * 128 + ((c16 * 16) ^ ((r0 & 7) * 16)));

    // -------- prologue: fill stages 0..NSTAGE-2 ------------------------------
    #pragma unroll
    for (int pre = 0; pre < NSTAGE - 1; pre++) {
        const uint32_t stg = sb + pre * STAGE_BYTES;
        const int koff = pre * BK;
        #pragma unroll
        for (int j = 0; j < NCHUNK; j++)
            cpasync16(stg + dst0 + 2048 * j, srcA0 + (size_t)16 * j * DIN + koff);
        #pragma unroll
        for (int j = 0; j < NCHUNK; j++)
            cpasync16(stg + A_STAGE_BYTES + dst0 + 2048 * j,
                      srcB0 + (size_t)16 * j * DIN + koff);
        asm volatile("cp.async.commit_group;" ::: "memory");
    }

    // -------- compute warp coordinates + ldmatrix lane addressing -----------
    const int wm0 = (wid & 1) * WM;      // 0/64
    const int wn0 = (wid >> 1) * WN;     // 0/64
    const int r8 = lane & 7;
    const uint32_t maskL = (uint32_t)(r8 * 16);
    const int aRow = wm0 + ((lane >> 3) & 1) * 8 + r8;
    const uint32_t aHi16 = (uint32_t)(((lane >> 4) & 1) * 16);
    const uint32_t aRowByte = (uint32_t)(aRow * 128);
    const int bRow = wn0 + ((lane >> 4) & 1) * 8 + r8;
    const uint32_t bHi16 = (uint32_t)(((lane >> 3) & 1) * 16);
    const uint32_t bRowByte = (uint32_t)(A_STAGE_BYTES + bRow * 128);

    float acc[WM / 16][WN / 8][4];   // [4][8][4] = 128 regs
    #pragma unroll
    for (int mt = 0; mt < WM / 16; mt++)
        #pragma unroll
        for (int nt = 0; nt < WN / 8; nt++)
            #pragma unroll
            for (int q = 0; q < 4; q++) acc[mt][nt][q] = 0.0f;

    // -------- main loop ------------------------------------------------------
    int slot = 0;
    int slot2 = NSTAGE - 1;
    for (int ki = 0; ki < NK; ki++) {
        asm volatile("cp.async.wait_group %0;" :: "n"(NSTAGE - 2) : "memory");
        __syncthreads();

        const uint32_t stg = sb + slot * STAGE_BYTES;
        #pragma unroll
        for (int kk = 0; kk < BK / 16; kk++) {
            const uint32_t aCol = ((uint32_t)(kk * 32) + aHi16) ^ maskL;
            const uint32_t bCol = ((uint32_t)(kk * 32) + bHi16) ^ maskL;
            uint32_t afr[WM / 16][4];
            uint32_t bfr[WN / 8][2];
            #pragma unroll
            for (int mt = 0; mt < WM / 16; mt++)
                ldsm_x4(afr[mt], stg + aRowByte + mt * 2048 + aCol);
            #pragma unroll
            for (int p = 0; p < WN / 16; p++)
                ldsm_x4(&bfr[2 * p][0], stg + bRowByte + p * 2048 + bCol);
            #pragma unroll
            for (int mt = 0; mt < WM / 16; mt++)
                #pragma unroll
                for (int nt = 0; nt < WN / 8; nt++)
                    mma_f16(acc[mt][nt], afr[mt], bfr[nt]);
        }

        // issue loads for chunk ki+NSTAGE-1 into the slot freed last iteration
        const int nk2 = ki + NSTAGE - 1;
        if (nk2 < NK) {
            const uint32_t stg2 = sb + slot2 * STAGE_BYTES;
            const int koff = nk2 * BK;
            #pragma unroll
            for (int j = 0; j < NCHUNK; j++)
                cpasync16(stg2 + dst0 + 2048 * j, srcA0 + (size_t)16 * j * DIN + koff);
            #pragma unroll
            for (int j = 0; j < NCHUNK; j++)
                cpasync16(stg2 + A_STAGE_BYTES + dst0 + 2048 * j,
                          srcB0 + (size_t)16 * j * DIN + koff);
        }
        asm volatile("cp.async.commit_group;" ::: "memory");

        if (++slot == NSTAGE) slot = 0;
        if (++slot2 == NSTAGE) slot2 = 0;
    }

    // -------- epilogue: bias + store ----------------------------------------
    #pragma unroll
    for (int mt = 0; mt < WM / 16; mt++) {
        const int row0 = m0 + wm0 + mt * 16 + lr;
        float* o0 = out + (size_t)row0 * DOUT;
        float* o1 = o0 + (size_t)8 * DOUT;
        #pragma unroll
        for (int nt = 0; nt < WN / 8; nt++) {
            const int col = n0 + wn0 + nt * 8 + 2 * lc;
            const float2 bv = *reinterpret_cast<const float2*>(&bias[col]);
            float2 v0, v1;
            v0.x = acc[mt][nt][0] + bv.x;  v0.y = acc[mt][nt][1] + bv.y;
            v1.x = acc[mt][nt][2] + bv.x;  v1.y = acc[mt][nt][3] + bv.y;
            *reinterpret_cast<float2*>(o0 + col) = v0;
            *reinterpret_cast<float2*>(o1 + col) = v1;
        }
    }
}

// ============================================================================
// Host launch
// ============================================================================
extern "C" void kernel_launch(void* const* d_in, const int* in_sizes, int n_in,
                              void* d_out, int out_size) {
    const float* x    = (const float*)d_in[0];
    const float* w    = (const float*)d_in[1];
    const float* bias = (const float*)d_in[2];
    float* out        = (float*)d_out;

    __half *dA = nullptr, *dB = nullptr;
    cudaGetSymbolAddress((void**)&dA, g_A);
    cudaGetSymbolAddress((void**)&dB, g_B);

    // 1) fused FWHT + W-conversion (overlapped DRAM phases)
    prep_kernel<<<TOKENS + WCONV_BLOCKS, 256>>>(x, (const float4*)w, dA, dB);

    // 2) GEMM (4 warps x 64x64, 2 CTAs/SM, ldmatrix fragments)
    cudaFuncSetAttribute(gemm_kernel, cudaFuncAttributeMaxDynamicSharedMemorySize, SMEM_TOTAL);
    dim3 grid((TOKENS / BM) * (DOUT / BN));  // 4096 CTAs, group-swizzled 1D
    gemm_kernel<<<grid, NTHREADS, SMEM_TOTAL>>>(dA, dB, bias, out);
}